// round 1
// baseline (speedup 1.0000x reference)
#include <cuda_runtime.h>
#include <cuda_bf16.h>
#include <math.h>

// Problem dims
#define BB   4
#define SS   2048
#define DD   1024
#define HH   16
#define FF   4096
#define MROWS (BB*SS)          // 8192
#define NBLK (SS/64)           // 32

// ---------------- scratch (device globals; no allocation allowed) ----------
__device__ float g_x1[MROWS*DD];   // LN1 output; reused as attention O
__device__ float g_q [MROWS*DD];   // Q; reused as x2 (LN2 output)
__device__ float g_k [MROWS*DD];
__device__ float g_v [MROWS*DD];
__device__ float g_h [MROWS*DD];   // residual stream after attention
__device__ float g_ff[MROWS*FF];   // GELU MLP intermediate

// ---------------- LayerNorm (one block per row, D=1024) --------------------
__global__ __launch_bounds__(256) void ln_kernel(
    const float* __restrict__ x, const float* __restrict__ g,
    const float* __restrict__ b, float* __restrict__ y)
{
    __shared__ float rs[8], rq[8];
    int row = blockIdx.x, t = threadIdx.x;
    const float4* xr = reinterpret_cast<const float4*>(x) + (size_t)row * 256;
    float4 v = xr[t];
    float s = v.x + v.y + v.z + v.w;
    float q = fmaf(v.x, v.x, fmaf(v.y, v.y, fmaf(v.z, v.z, v.w * v.w)));
    #pragma unroll
    for (int o = 16; o; o >>= 1) {
        s += __shfl_xor_sync(0xffffffffu, s, o);
        q += __shfl_xor_sync(0xffffffffu, q, o);
    }
    if ((t & 31) == 0) { rs[t >> 5] = s; rq[t >> 5] = q; }
    __syncthreads();
    float ts = 0.f, tq = 0.f;
    #pragma unroll
    for (int i = 0; i < 8; i++) { ts += rs[i]; tq += rq[i]; }
    float mean = ts * (1.0f / 1024.0f);
    float var  = tq * (1.0f / 1024.0f) - mean * mean;
    float inv  = rsqrtf(var + 1e-5f);
    float4 gg = reinterpret_cast<const float4*>(g)[t];
    float4 bb = reinterpret_cast<const float4*>(b)[t];
    float4 o4;
    o4.x = (v.x - mean) * inv * gg.x + bb.x;
    o4.y = (v.y - mean) * inv * gg.y + bb.y;
    o4.z = (v.z - mean) * inv * gg.z + bb.z;
    o4.w = (v.w - mean) * inv * gg.w + bb.w;
    reinterpret_cast<float4*>(y)[(size_t)row * 256 + t] = o4;
}

// ---------------- SGEMM: C = A(MxK) @ B(KxN) + bias, optional epilogue -----
// EPI: 0 = bias only, 1 = bias + residual add, 2 = bias + exact GELU
#define BM 128
#define BN 128
#define BK 16
template<int EPI>
__global__ __launch_bounds__(256) void sgemm(
    const float* __restrict__ A, const float* __restrict__ B,
    const float* __restrict__ bias, const float* __restrict__ res,
    float* __restrict__ C, int M, int N, int K)
{
    __shared__ __align__(16) float As[BK][BM + 4];
    __shared__ __align__(16) float Bs[BK][BN + 4];
    int tid = threadIdx.x;
    int bm = blockIdx.y * BM;
    int bn = blockIdx.x * BN;
    int tx = tid & 15, ty = tid >> 4;

    float acc[8][8];
    #pragma unroll
    for (int i = 0; i < 8; i++)
        #pragma unroll
        for (int j = 0; j < 8; j++) acc[i][j] = 0.f;

    for (int k0 = 0; k0 < K; k0 += BK) {
        #pragma unroll
        for (int i = 0; i < 2; i++) {
            int id = tid + i * 256;
            int r = id >> 2, c4 = (id & 3) << 2;
            float4 a = *reinterpret_cast<const float4*>(
                &A[(size_t)(bm + r) * K + k0 + c4]);
            As[c4 + 0][r] = a.x; As[c4 + 1][r] = a.y;
            As[c4 + 2][r] = a.z; As[c4 + 3][r] = a.w;
            int rb = id >> 5, cb4 = (id & 31) << 2;
            float4 bvec = *reinterpret_cast<const float4*>(
                &B[(size_t)(k0 + rb) * N + bn + cb4]);
            *reinterpret_cast<float4*>(&Bs[rb][cb4]) = bvec;
        }
        __syncthreads();
        #pragma unroll
        for (int kk = 0; kk < BK; kk++) {
            float af[8], bf[8];
            *reinterpret_cast<float4*>(&af[0]) =
                *reinterpret_cast<const float4*>(&As[kk][ty * 8 + 0]);
            *reinterpret_cast<float4*>(&af[4]) =
                *reinterpret_cast<const float4*>(&As[kk][ty * 8 + 4]);
            *reinterpret_cast<float4*>(&bf[0]) =
                *reinterpret_cast<const float4*>(&Bs[kk][tx * 8 + 0]);
            *reinterpret_cast<float4*>(&bf[4]) =
                *reinterpret_cast<const float4*>(&Bs[kk][tx * 8 + 4]);
            #pragma unroll
            for (int i = 0; i < 8; i++)
                #pragma unroll
                for (int j = 0; j < 8; j++)
                    acc[i][j] = fmaf(af[i], bf[j], acc[i][j]);
        }
        __syncthreads();
    }

    #pragma unroll
    for (int i = 0; i < 8; i++) {
        int row = bm + ty * 8 + i;
        #pragma unroll
        for (int j4 = 0; j4 < 2; j4++) {
            int col = bn + tx * 8 + j4 * 4;
            float4 o;
            float* pv = &acc[i][j4 * 4];
            o.x = pv[0] + bias[col + 0];
            o.y = pv[1] + bias[col + 1];
            o.z = pv[2] + bias[col + 2];
            o.w = pv[3] + bias[col + 3];
            if (EPI == 1) {
                float4 r = *reinterpret_cast<const float4*>(
                    &res[(size_t)row * N + col]);
                o.x += r.x; o.y += r.y; o.z += r.z; o.w += r.w;
            }
            if (EPI == 2) {
                o.x = 0.5f * o.x * (1.0f + erff(o.x * 0.70710678118654752f));
                o.y = 0.5f * o.y * (1.0f + erff(o.y * 0.70710678118654752f));
                o.z = 0.5f * o.z * (1.0f + erff(o.z * 0.70710678118654752f));
                o.w = 0.5f * o.w * (1.0f + erff(o.w * 0.70710678118654752f));
            }
            *reinterpret_cast<float4*>(&C[(size_t)row * N + col]) = o;
        }
    }
}

// ---------------- block-sparse attention (one CTA per (b,h,block)) ---------
// Q/K/V/O are row-major [8192][1024]; block = 64 tokens x 64 headdim.
__global__ __launch_bounds__(256) void attention_kernel(
    const float* __restrict__ Q, const float* __restrict__ K,
    const float* __restrict__ V, float* __restrict__ O,
    float* __restrict__ W)
{
    __shared__ float qs[64][65];
    __shared__ float ks[64][65];
    int tid = threadIdx.x;
    int blk = blockIdx.x;                    // b*512 + h*32 + n
    int n = blk & 31, hh = (blk >> 5) & 15, b = blk >> 9;
    size_t base = ((size_t)(b * SS + n * 64)) * DD + hh * 64;

    for (int i = tid; i < 4096; i += 256) {
        int r = i >> 6, c = i & 63;
        qs[r][c] = Q[base + (size_t)r * DD + c] * 0.125f;  // 1/sqrt(64)
        ks[r][c] = K[base + (size_t)r * DD + c];
    }
    __syncthreads();

    int qi  = tid >> 2;
    int kj0 = (tid & 3) << 4;
    float w[16];
    #pragma unroll
    for (int j = 0; j < 16; j++) {
        float acc = 0.f;
        #pragma unroll
        for (int d = 0; d < 64; d++)
            acc = fmaf(qs[qi][d], ks[kj0 + j][d], acc);
        w[j] = acc;
    }
    // softmax over row qi, spread across the 4-lane group (lanes xor 1,2)
    float m = w[0];
    #pragma unroll
    for (int j = 1; j < 16; j++) m = fmaxf(m, w[j]);
    m = fmaxf(m, __shfl_xor_sync(0xffffffffu, m, 1));
    m = fmaxf(m, __shfl_xor_sync(0xffffffffu, m, 2));
    float s = 0.f;
    #pragma unroll
    for (int j = 0; j < 16; j++) { w[j] = __expf(w[j] - m); s += w[j]; }
    s += __shfl_xor_sync(0xffffffffu, s, 1);
    s += __shfl_xor_sync(0xffffffffu, s, 2);
    float inv = 1.0f / s;
    #pragma unroll
    for (int j = 0; j < 16; j++) w[j] *= inv;

    if (W) {
        float* wout = W + (size_t)blk * 4096 + qi * 64 + kj0;
        #pragma unroll
        for (int j = 0; j < 16; j++) wout[j] = w[j];
    }

    __syncthreads();                          // done reading qs (scores)
    for (int i = tid; i < 4096; i += 256) {   // V into qs
        int r = i >> 6, c = i & 63;
        qs[r][c] = V[base + (size_t)r * DD + c];
    }
    __syncthreads();

    #pragma unroll
    for (int dc = 0; dc < 4; dc++) {
        float p[16];
        #pragma unroll
        for (int jj = 0; jj < 16; jj++) {
            int d = dc * 16 + jj;
            float acc = 0.f;
            #pragma unroll
            for (int j = 0; j < 16; j++)
                acc = fmaf(w[j], qs[kj0 + j][d], acc);
            p[jj] = acc;
        }
        #pragma unroll
        for (int jj = 0; jj < 16; jj++) {
            p[jj] += __shfl_xor_sync(0xffffffffu, p[jj], 1);
            p[jj] += __shfl_xor_sync(0xffffffffu, p[jj], 2);
        }
        if ((tid & 3) == dc) {
            #pragma unroll
            for (int jj = 0; jj < 16; jj++)
                O[base + (size_t)qi * DD + dc * 16 + jj] = p[jj];
        }
    }
}

// ---------------- host launcher ---------------------------------------------
extern "C" void kernel_launch(void* const* d_in, const int* in_sizes, int n_in,
                              void* d_out, int out_size)
{
    const float* hidden = (const float*)d_in[0];
    const float* ln1_g  = (const float*)d_in[1];
    const float* ln1_b  = (const float*)d_in[2];
    const float* ln2_g  = (const float*)d_in[3];
    const float* ln2_b  = (const float*)d_in[4];
    const float* wq = (const float*)d_in[5];  const float* bq = (const float*)d_in[6];
    const float* wk = (const float*)d_in[7];  const float* bk = (const float*)d_in[8];
    const float* wv = (const float*)d_in[9];  const float* bv = (const float*)d_in[10];
    const float* wo = (const float*)d_in[11]; const float* bo = (const float*)d_in[12];
    const float* w1 = (const float*)d_in[13]; const float* b1 = (const float*)d_in[14];
    const float* w2 = (const float*)d_in[15]; const float* b2 = (const float*)d_in[16];
    float* out = (float*)d_out;

    float *x1, *q, *k, *v, *h, *ff;
    cudaGetSymbolAddress((void**)&x1, g_x1);
    cudaGetSymbolAddress((void**)&q,  g_q);
    cudaGetSymbolAddress((void**)&k,  g_k);
    cudaGetSymbolAddress((void**)&v,  g_v);
    cudaGetSymbolAddress((void**)&h,  g_h);
    cudaGetSymbolAddress((void**)&ff, g_ff);

    const int MAIN_ELEMS = MROWS * DD;                 // 8388608
    const int ATTW_ELEMS = BB * HH * NBLK * 64 * 64;   // 8388608
    float* attw = (out_size >= MAIN_ELEMS + ATTW_ELEMS) ? out + MAIN_ELEMS
                                                        : nullptr;

    dim3 gD(DD / BN, MROWS / BM);   // (8, 64)
    dim3 gF(FF / BN, MROWS / BM);   // (32, 64)

    // x1 = LN1(hidden)
    ln_kernel<<<MROWS, 256>>>(hidden, ln1_g, ln1_b, x1);
    // q/k/v = x1 @ w{q,k,v} + b
    sgemm<0><<<gD, 256>>>(x1, wq, bq, nullptr, q, MROWS, DD, DD);
    sgemm<0><<<gD, 256>>>(x1, wk, bk, nullptr, k, MROWS, DD, DD);
    sgemm<0><<<gD, 256>>>(x1, wv, bv, nullptr, v, MROWS, DD, DD);
    // block attention: O into x1 (x1 no longer needed); optional attn_w out
    attention_kernel<<<BB * HH * NBLK, 256>>>(q, k, v, x1, attw);
    // h = hidden + O @ wo + bo
    sgemm<1><<<gD, 256>>>(x1, wo, bo, hidden, h, MROWS, DD, DD);
    // x2 = LN2(h)  (into q, reuse)
    ln_kernel<<<MROWS, 256>>>(h, ln2_g, ln2_b, q);
    // ff = gelu(x2 @ w1 + b1)
    sgemm<2><<<gF, 256>>>(q, w1, b1, nullptr, ff, MROWS, FF, DD);
    // out = h + ff @ w2 + b2
    sgemm<1><<<gD, 256>>>(ff, w2, b2, h, out, MROWS, DD, FF);
}

// round 2
// speedup vs baseline: 1.0026x; 1.0026x over previous
#include <cuda_runtime.h>
#include <cuda_bf16.h>
#include <math.h>

// Problem dims
#define BB   4
#define SS   2048
#define DD   1024
#define HH   16
#define FF   4096
#define MROWS (BB*SS)          // 8192
#define NBLK (SS/64)           // 32

// ---------------- scratch (device globals; no allocation allowed) ----------
__device__ float g_x1[MROWS*DD];   // LN1 output; reused as attention O
__device__ float g_q [MROWS*DD];   // Q; reused as x2 (LN2 output)
__device__ float g_k [MROWS*DD];
__device__ float g_v [MROWS*DD];
__device__ float g_h [MROWS*DD];   // residual stream after attention
__device__ float g_ff[MROWS*FF];   // GELU MLP intermediate

// ---------------- LayerNorm (one block per row, D=1024) --------------------
__global__ __launch_bounds__(256) void ln_kernel(
    const float* __restrict__ x, const float* __restrict__ g,
    const float* __restrict__ b, float* __restrict__ y)
{
    __shared__ float rs[8], rq[8];
    int row = blockIdx.x, t = threadIdx.x;
    const float4* xr = reinterpret_cast<const float4*>(x) + (size_t)row * 256;
    float4 v = xr[t];
    float s = v.x + v.y + v.z + v.w;
    float q = fmaf(v.x, v.x, fmaf(v.y, v.y, fmaf(v.z, v.z, v.w * v.w)));
    #pragma unroll
    for (int o = 16; o; o >>= 1) {
        s += __shfl_xor_sync(0xffffffffu, s, o);
        q += __shfl_xor_sync(0xffffffffu, q, o);
    }
    if ((t & 31) == 0) { rs[t >> 5] = s; rq[t >> 5] = q; }
    __syncthreads();
    float ts = 0.f, tq = 0.f;
    #pragma unroll
    for (int i = 0; i < 8; i++) { ts += rs[i]; tq += rq[i]; }
    float mean = ts * (1.0f / 1024.0f);
    float var  = tq * (1.0f / 1024.0f) - mean * mean;
    float inv  = rsqrtf(var + 1e-5f);
    float4 gg = reinterpret_cast<const float4*>(g)[t];
    float4 bb = reinterpret_cast<const float4*>(b)[t];
    float4 o4;
    o4.x = (v.x - mean) * inv * gg.x + bb.x;
    o4.y = (v.y - mean) * inv * gg.y + bb.y;
    o4.z = (v.z - mean) * inv * gg.z + bb.z;
    o4.w = (v.w - mean) * inv * gg.w + bb.w;
    reinterpret_cast<float4*>(y)[(size_t)row * 256 + t] = o4;
}

// ---------------- SGEMM: C = A(MxK) @ B(KxN) + bias, optional epilogue -----
// EPI: 0 = bias only, 1 = bias + residual add, 2 = bias + exact GELU
#define BM 128
#define BN 128
#define BK 16
template<int EPI>
__global__ __launch_bounds__(256) void sgemm(
    const float* __restrict__ A, const float* __restrict__ B,
    const float* __restrict__ bias, const float* __restrict__ res,
    float* __restrict__ C, int M, int N, int K)
{
    __shared__ __align__(16) float As[BK][BM + 4];
    __shared__ __align__(16) float Bs[BK][BN + 4];
    int tid = threadIdx.x;
    int bm = blockIdx.y * BM;
    int bn = blockIdx.x * BN;
    int tx = tid & 15, ty = tid >> 4;

    float acc[8][8];
    #pragma unroll
    for (int i = 0; i < 8; i++)
        #pragma unroll
        for (int j = 0; j < 8; j++) acc[i][j] = 0.f;

    for (int k0 = 0; k0 < K; k0 += BK) {
        #pragma unroll
        for (int i = 0; i < 2; i++) {
            int id = tid + i * 256;
            int r = id >> 2, c4 = (id & 3) << 2;
            float4 a = *reinterpret_cast<const float4*>(
                &A[(size_t)(bm + r) * K + k0 + c4]);
            As[c4 + 0][r] = a.x; As[c4 + 1][r] = a.y;
            As[c4 + 2][r] = a.z; As[c4 + 3][r] = a.w;
            int rb = id >> 5, cb4 = (id & 31) << 2;
            float4 bvec = *reinterpret_cast<const float4*>(
                &B[(size_t)(k0 + rb) * N + bn + cb4]);
            *reinterpret_cast<float4*>(&Bs[rb][cb4]) = bvec;
        }
        __syncthreads();
        #pragma unroll
        for (int kk = 0; kk < BK; kk++) {
            float af[8], bf[8];
            *reinterpret_cast<float4*>(&af[0]) =
                *reinterpret_cast<const float4*>(&As[kk][ty * 8 + 0]);
            *reinterpret_cast<float4*>(&af[4]) =
                *reinterpret_cast<const float4*>(&As[kk][ty * 8 + 4]);
            *reinterpret_cast<float4*>(&bf[0]) =
                *reinterpret_cast<const float4*>(&Bs[kk][tx * 8 + 0]);
            *reinterpret_cast<float4*>(&bf[4]) =
                *reinterpret_cast<const float4*>(&Bs[kk][tx * 8 + 4]);
            #pragma unroll
            for (int i = 0; i < 8; i++)
                #pragma unroll
                for (int j = 0; j < 8; j++)
                    acc[i][j] = fmaf(af[i], bf[j], acc[i][j]);
        }
        __syncthreads();
    }

    #pragma unroll
    for (int i = 0; i < 8; i++) {
        int row = bm + ty * 8 + i;
        #pragma unroll
        for (int j4 = 0; j4 < 2; j4++) {
            int col = bn + tx * 8 + j4 * 4;
            float4 o;
            float* pv = &acc[i][j4 * 4];
            o.x = pv[0] + bias[col + 0];
            o.y = pv[1] + bias[col + 1];
            o.z = pv[2] + bias[col + 2];
            o.w = pv[3] + bias[col + 3];
            if (EPI == 1) {
                float4 r = *reinterpret_cast<const float4*>(
                    &res[(size_t)row * N + col]);
                o.x += r.x; o.y += r.y; o.z += r.z; o.w += r.w;
            }
            if (EPI == 2) {
                o.x = 0.5f * o.x * (1.0f + erff(o.x * 0.70710678118654752f));
                o.y = 0.5f * o.y * (1.0f + erff(o.y * 0.70710678118654752f));
                o.z = 0.5f * o.z * (1.0f + erff(o.z * 0.70710678118654752f));
                o.w = 0.5f * o.w * (1.0f + erff(o.w * 0.70710678118654752f));
            }
            *reinterpret_cast<float4*>(&C[(size_t)row * N + col]) = o;
        }
    }
}

// ---------------- block-sparse attention (one CTA per (b,h,block)) ---------
// Q/K/V/O are row-major [8192][1024]; block = 64 tokens x 64 headdim.
__global__ __launch_bounds__(256) void attention_kernel(
    const float* __restrict__ Q, const float* __restrict__ K,
    const float* __restrict__ V, float* __restrict__ O,
    float* __restrict__ W)
{
    __shared__ float qs[64][65];
    __shared__ float ks[64][65];
    int tid = threadIdx.x;
    int blk = blockIdx.x;                    // b*512 + h*32 + n
    int n = blk & 31, hh = (blk >> 5) & 15, b = blk >> 9;
    size_t base = ((size_t)(b * SS + n * 64)) * DD + hh * 64;

    for (int i = tid; i < 4096; i += 256) {
        int r = i >> 6, c = i & 63;
        qs[r][c] = Q[base + (size_t)r * DD + c] * 0.125f;  // 1/sqrt(64)
        ks[r][c] = K[base + (size_t)r * DD + c];
    }
    __syncthreads();

    int qi  = tid >> 2;
    int kj0 = (tid & 3) << 4;
    float w[16];
    #pragma unroll
    for (int j = 0; j < 16; j++) {
        float acc = 0.f;
        #pragma unroll
        for (int d = 0; d < 64; d++)
            acc = fmaf(qs[qi][d], ks[kj0 + j][d], acc);
        w[j] = acc;
    }
    // softmax over row qi, spread across the 4-lane group (lanes xor 1,2)
    float m = w[0];
    #pragma unroll
    for (int j = 1; j < 16; j++) m = fmaxf(m, w[j]);
    m = fmaxf(m, __shfl_xor_sync(0xffffffffu, m, 1));
    m = fmaxf(m, __shfl_xor_sync(0xffffffffu, m, 2));
    float s = 0.f;
    #pragma unroll
    for (int j = 0; j < 16; j++) { w[j] = __expf(w[j] - m); s += w[j]; }
    s += __shfl_xor_sync(0xffffffffu, s, 1);
    s += __shfl_xor_sync(0xffffffffu, s, 2);
    float inv = 1.0f / s;
    #pragma unroll
    for (int j = 0; j < 16; j++) w[j] *= inv;

    if (W) {
        float* wout = W + (size_t)blk * 4096 + qi * 64 + kj0;
        #pragma unroll
        for (int j = 0; j < 16; j++) wout[j] = w[j];
    }

    __syncthreads();                          // done reading qs (scores)
    for (int i = tid; i < 4096; i += 256) {   // V into qs
        int r = i >> 6, c = i & 63;
        qs[r][c] = V[base + (size_t)r * DD + c];
    }
    __syncthreads();

    #pragma unroll
    for (int dc = 0; dc < 4; dc++) {
        float p[16];
        #pragma unroll
        for (int jj = 0; jj < 16; jj++) {
            int d = dc * 16 + jj;
            float acc = 0.f;
            #pragma unroll
            for (int j = 0; j < 16; j++)
                acc = fmaf(w[j], qs[kj0 + j][d], acc);
            p[jj] = acc;
        }
        #pragma unroll
        for (int jj = 0; jj < 16; jj++) {
            p[jj] += __shfl_xor_sync(0xffffffffu, p[jj], 1);
            p[jj] += __shfl_xor_sync(0xffffffffu, p[jj], 2);
        }
        if ((tid & 3) == dc) {
            #pragma unroll
            for (int jj = 0; jj < 16; jj++)
                O[base + (size_t)qi * DD + dc * 16 + jj] = p[jj];
        }
    }
}

// ---------------- host launcher ---------------------------------------------
extern "C" void kernel_launch(void* const* d_in, const int* in_sizes, int n_in,
                              void* d_out, int out_size)
{
    const float* hidden = (const float*)d_in[0];
    const float* ln1_g  = (const float*)d_in[1];
    const float* ln1_b  = (const float*)d_in[2];
    const float* ln2_g  = (const float*)d_in[3];
    const float* ln2_b  = (const float*)d_in[4];
    const float* wq = (const float*)d_in[5];  const float* bq = (const float*)d_in[6];
    const float* wk = (const float*)d_in[7];  const float* bk = (const float*)d_in[8];
    const float* wv = (const float*)d_in[9];  const float* bv = (const float*)d_in[10];
    const float* wo = (const float*)d_in[11]; const float* bo = (const float*)d_in[12];
    const float* w1 = (const float*)d_in[13]; const float* b1 = (const float*)d_in[14];
    const float* w2 = (const float*)d_in[15]; const float* b2 = (const float*)d_in[16];
    float* out = (float*)d_out;

    float *x1, *q, *k, *v, *h, *ff;
    cudaGetSymbolAddress((void**)&x1, g_x1);
    cudaGetSymbolAddress((void**)&q,  g_q);
    cudaGetSymbolAddress((void**)&k,  g_k);
    cudaGetSymbolAddress((void**)&v,  g_v);
    cudaGetSymbolAddress((void**)&h,  g_h);
    cudaGetSymbolAddress((void**)&ff, g_ff);

    const int MAIN_ELEMS = MROWS * DD;                 // 8388608
    const int ATTW_ELEMS = BB * HH * NBLK * 64 * 64;   // 8388608
    float* attw = (out_size >= MAIN_ELEMS + ATTW_ELEMS) ? out + MAIN_ELEMS
                                                        : nullptr;

    dim3 gD(DD / BN, MROWS / BM);   // (8, 64)
    dim3 gF(FF / BN, MROWS / BM);   // (32, 64)

    // x1 = LN1(hidden)
    ln_kernel<<<MROWS, 256>>>(hidden, ln1_g, ln1_b, x1);
    // q/k/v = x1 @ w{q,k,v} + b
    sgemm<0><<<gD, 256>>>(x1, wq, bq, nullptr, q, MROWS, DD, DD);
    sgemm<0><<<gD, 256>>>(x1, wk, bk, nullptr, k, MROWS, DD, DD);
    sgemm<0><<<gD, 256>>>(x1, wv, bv, nullptr, v, MROWS, DD, DD);
    // block attention: O into x1 (x1 no longer needed); optional attn_w out
    attention_kernel<<<BB * HH * NBLK, 256>>>(q, k, v, x1, attw);
    // h = hidden + O @ wo + bo
    sgemm<1><<<gD, 256>>>(x1, wo, bo, hidden, h, MROWS, DD, DD);
    // x2 = LN2(h)  (into q, reuse)
    ln_kernel<<<MROWS, 256>>>(h, ln2_g, ln2_b, q);
    // ff = gelu(x2 @ w1 + b1)
    sgemm<2><<<gF, 256>>>(q, w1, b1, nullptr, ff, MROWS, FF, DD);
    // out = h + ff @ w2 + b2
    sgemm<1><<<gD, 256>>>(ff, w2, b2, h, out, MROWS, DD, FF);
}

// round 4
// speedup vs baseline: 2.8124x; 2.8050x over previous
#include <cuda_runtime.h>
#include <cuda_bf16.h>
#include <cstdint>
#include <math.h>

// Problem dims
#define BB   4
#define SS   2048
#define DD   1024
#define HH   16
#define FF   4096
#define MROWS (BB*SS)          // 8192
#define NBLK (SS/64)           // 32

// ---------------- scratch (device globals; no allocation allowed) ----------
__device__ float g_x1[MROWS*DD];   // LN1 output; reused as attention O
__device__ float g_q [MROWS*DD];   // Q; reused as x2 (LN2 output)
__device__ float g_k [MROWS*DD];
__device__ float g_v [MROWS*DD];
__device__ float g_h [MROWS*DD];   // residual stream after attention
__device__ float g_ff[MROWS*FF];   // GELU MLP intermediate
// transposed weights (N-major "Bt[n][k]" for the mma B operand)
__device__ float g_wqT[DD*DD];
__device__ float g_wkT[DD*DD];
__device__ float g_wvT[DD*DD];
__device__ float g_woT[DD*DD];
__device__ float g_w1T[FF*DD];     // [4096][1024]
__device__ float g_w2T[DD*FF];     // [1024][4096]

// ---------------- PTX helpers (base-target-safe only) -----------------------
__device__ __forceinline__ uint32_t smem_u32(const void* p) {
    uint32_t a;
    asm("{ .reg .u64 t; cvta.to.shared.u64 t, %1; cvt.u32.u64 %0, t; }"
        : "=r"(a) : "l"(p));
    return a;
}
__device__ __forceinline__ void cp16(uint32_t dst, const void* src) {
    asm volatile("cp.async.cg.shared.global [%0], [%1], 16;"
                 :: "r"(dst), "l"(src) : "memory");
}
#define CP_COMMIT() asm volatile("cp.async.commit_group;" ::: "memory")
#define CP_WAIT(n)  asm volatile("cp.async.wait_group %0;" :: "n"(n) : "memory")

__device__ __forceinline__ void mma_tf32(float* d, const uint32_t* a,
                                         const uint32_t* b) {
    asm volatile(
        "mma.sync.aligned.m16n8k8.row.col.f32.tf32.tf32.f32 "
        "{%0,%1,%2,%3}, {%4,%5,%6,%7}, {%8,%9}, {%0,%1,%2,%3};"
        : "+f"(d[0]), "+f"(d[1]), "+f"(d[2]), "+f"(d[3])
        : "r"(a[0]), "r"(a[1]), "r"(a[2]), "r"(a[3]), "r"(b[0]), "r"(b[1]));
}

// ---------------- LayerNorm (one block per row, D=1024) --------------------
__global__ __launch_bounds__(256) void ln_kernel(
    const float* __restrict__ x, const float* __restrict__ g,
    const float* __restrict__ b, float* __restrict__ y)
{
    __shared__ float rs[8], rq[8];
    int row = blockIdx.x, t = threadIdx.x;
    const float4* xr = reinterpret_cast<const float4*>(x) + (size_t)row * 256;
    float4 v = xr[t];
    float s = v.x + v.y + v.z + v.w;
    float q = fmaf(v.x, v.x, fmaf(v.y, v.y, fmaf(v.z, v.z, v.w * v.w)));
    #pragma unroll
    for (int o = 16; o; o >>= 1) {
        s += __shfl_xor_sync(0xffffffffu, s, o);
        q += __shfl_xor_sync(0xffffffffu, q, o);
    }
    if ((t & 31) == 0) { rs[t >> 5] = s; rq[t >> 5] = q; }
    __syncthreads();
    float ts = 0.f, tq = 0.f;
    #pragma unroll
    for (int i = 0; i < 8; i++) { ts += rs[i]; tq += rq[i]; }
    float mean = ts * (1.0f / 1024.0f);
    float var  = tq * (1.0f / 1024.0f) - mean * mean;
    float inv  = rsqrtf(var + 1e-5f);
    float4 gg = reinterpret_cast<const float4*>(g)[t];
    float4 bb = reinterpret_cast<const float4*>(b)[t];
    float4 o4;
    o4.x = (v.x - mean) * inv * gg.x + bb.x;
    o4.y = (v.y - mean) * inv * gg.y + bb.y;
    o4.z = (v.z - mean) * inv * gg.z + bb.z;
    o4.w = (v.w - mean) * inv * gg.w + bb.w;
    reinterpret_cast<float4*>(y)[(size_t)row * 256 + t] = o4;
}

// ---------------- weight transpose: in[K][N] -> out[N][K] -------------------
__global__ __launch_bounds__(256) void transpose_kernel(
    const float* __restrict__ in, float* __restrict__ out, int K, int N)
{
    __shared__ float t[32][33];
    int tx = threadIdx.x, ty = threadIdx.y;        // 32 x 8
    int bn = blockIdx.x * 32, bk = blockIdx.y * 32;
    #pragma unroll
    for (int i = 0; i < 4; i++)
        t[ty + 8 * i][tx] = in[(size_t)(bk + ty + 8 * i) * N + bn + tx];
    __syncthreads();
    #pragma unroll
    for (int i = 0; i < 4; i++)
        out[(size_t)(bn + ty + 8 * i) * K + bk + tx] = t[tx][ty + 8 * i];
}

// ---------------- tf32 mma.sync GEMM ----------------------------------------
// C[M,N] = A[M,K] @ Bt[N,K]^T + bias, epilogue
// EPI: 0 = bias, 1 = bias + residual, 2 = bias + exact GELU
// CTA tile 128x128, K-chunk 32, cp.async double buffer.
// SMEM layout: rows of 36 floats (conflict-free fragment loads).
#define LDS36 36
#define TILE_F (128 * LDS36)            // 4608 floats per tile
#define SMEM_BYTES (4 * TILE_F * 4)     // 73728 bytes

template<int EPI>
__global__ __launch_bounds__(256, 2) void tgemm(
    const float* __restrict__ A, const float* __restrict__ Bt,
    const float* __restrict__ bias, const float* __restrict__ res,
    float* __restrict__ C, int M, int N, int K)
{
    extern __shared__ float smf[];
    const uint32_t sbase = smem_u32(smf);
    const int tid  = threadIdx.x;
    const int wid  = tid >> 5;
    const int lane = tid & 31;
    const int g    = lane >> 2;        // groupID
    const int c    = lane & 3;         // threadID_in_group
    const int warp_m = wid & 3;        // 4 warps down M (32 rows each)
    const int warp_n = wid >> 2;       // 2 warps across N (64 cols each)
    const int bm = blockIdx.y * 128;
    const int bn = blockIdx.x * 128;

    // loader coords: 4 float4 per tile per thread
    const int r0 = tid >> 3;           // rows r0, r0+32, r0+64, r0+96
    const int u0 = tid & 7;            // 16B slot within 32-float row chunk

    // smem float-index bases: As[p] = p*2*TILE_F, Bs[p] = p*2*TILE_F + TILE_F
    const uint32_t bytesA[2] = { sbase, sbase + 2u * TILE_F * 4u };
    const uint32_t bytesB[2] = { sbase + TILE_F * 4u, sbase + 3u * TILE_F * 4u };

    float acc[2][8][4];
    #pragma unroll
    for (int i = 0; i < 2; i++)
        #pragma unroll
        for (int j = 0; j < 8; j++)
            #pragma unroll
            for (int r = 0; r < 4; r++) acc[i][j][r] = 0.f;

    const int NK = K >> 5;

    // prologue: chunk 0 -> buffer 0
    #pragma unroll
    for (int t = 0; t < 4; t++) {
        int row = r0 + 32 * t;
        uint32_t soff = (uint32_t)(row * LDS36 + u0 * 4) * 4u;
        cp16(bytesA[0] + soff, A  + (size_t)(bm + row) * K + u0 * 4);
        cp16(bytesB[0] + soff, Bt + (size_t)(bn + row) * K + u0 * 4);
    }
    CP_COMMIT();

    for (int k = 0; k < NK; k++) {
        const int p = k & 1;
        if (k + 1 < NK) {
            const int k0 = (k + 1) << 5;
            #pragma unroll
            for (int t = 0; t < 4; t++) {
                int row = r0 + 32 * t;
                uint32_t soff = (uint32_t)(row * LDS36 + u0 * 4) * 4u;
                cp16(bytesA[p ^ 1] + soff, A  + (size_t)(bm + row) * K + k0 + u0 * 4);
                cp16(bytesB[p ^ 1] + soff, Bt + (size_t)(bn + row) * K + k0 + u0 * 4);
            }
            CP_COMMIT();
            CP_WAIT(1);
        } else {
            CP_WAIT(0);
        }
        __syncthreads();

        const float* As = smf + p * 2 * TILE_F;
        const float* Bs = smf + p * 2 * TILE_F + TILE_F;

        #pragma unroll
        for (int ks = 0; ks < 4; ks++) {
            const int k0 = ks * 8;
            uint32_t afr[2][4], bfr[8][2];
            #pragma unroll
            for (int im = 0; im < 2; im++) {
                const int r = warp_m * 32 + im * 16;
                afr[im][0] = __float_as_uint(As[(r + g    ) * LDS36 + k0 + c    ]);
                afr[im][1] = __float_as_uint(As[(r + g + 8) * LDS36 + k0 + c    ]);
                afr[im][2] = __float_as_uint(As[(r + g    ) * LDS36 + k0 + c + 4]);
                afr[im][3] = __float_as_uint(As[(r + g + 8) * LDS36 + k0 + c + 4]);
            }
            #pragma unroll
            for (int in = 0; in < 8; in++) {
                const int n = warp_n * 64 + in * 8;
                bfr[in][0] = __float_as_uint(Bs[(n + g) * LDS36 + k0 + c    ]);
                bfr[in][1] = __float_as_uint(Bs[(n + g) * LDS36 + k0 + c + 4]);
            }
            #pragma unroll
            for (int im = 0; im < 2; im++)
                #pragma unroll
                for (int in = 0; in < 8; in++)
                    mma_tf32(acc[im][in], afr[im], bfr[in]);
        }
        __syncthreads();
    }

    // ---- epilogue ----
    #pragma unroll
    for (int im = 0; im < 2; im++) {
        #pragma unroll
        for (int half = 0; half < 2; half++) {
            const int row = bm + warp_m * 32 + im * 16 + g + half * 8;
            #pragma unroll
            for (int in = 0; in < 8; in++) {
                const int col = bn + warp_n * 64 + in * 8 + 2 * c;
                float v0 = acc[im][in][half * 2 + 0] + bias[col];
                float v1 = acc[im][in][half * 2 + 1] + bias[col + 1];
                if (EPI == 1) {
                    const float2 rr = *reinterpret_cast<const float2*>(
                        &res[(size_t)row * N + col]);
                    v0 += rr.x; v1 += rr.y;
                }
                if (EPI == 2) {
                    v0 = 0.5f * v0 * (1.0f + erff(v0 * 0.70710678118654752f));
                    v1 = 0.5f * v1 * (1.0f + erff(v1 * 0.70710678118654752f));
                }
                float2 o2 = make_float2(v0, v1);
                *reinterpret_cast<float2*>(&C[(size_t)row * N + col]) = o2;
            }
        }
    }
}

// ---------------- block-sparse attention (one CTA per (b,h,block)) ---------
__global__ __launch_bounds__(256) void attention_kernel(
    const float* __restrict__ Q, const float* __restrict__ K,
    const float* __restrict__ V, float* __restrict__ O,
    float* __restrict__ W)
{
    __shared__ float qs[64][65];
    __shared__ float ks[64][65];
    int tid = threadIdx.x;
    int blk = blockIdx.x;                    // b*512 + h*32 + n
    int n = blk & 31, hh = (blk >> 5) & 15, b = blk >> 9;
    size_t base = ((size_t)(b * SS + n * 64)) * DD + hh * 64;

    for (int i = tid; i < 4096; i += 256) {
        int r = i >> 6, c = i & 63;
        qs[r][c] = Q[base + (size_t)r * DD + c] * 0.125f;  // 1/sqrt(64)
        ks[r][c] = K[base + (size_t)r * DD + c];
    }
    __syncthreads();

    int qi  = tid >> 2;
    int kj0 = (tid & 3) << 4;
    float w[16];
    #pragma unroll
    for (int j = 0; j < 16; j++) {
        float acc = 0.f;
        #pragma unroll
        for (int d = 0; d < 64; d++)
            acc = fmaf(qs[qi][d], ks[kj0 + j][d], acc);
        w[j] = acc;
    }
    float m = w[0];
    #pragma unroll
    for (int j = 1; j < 16; j++) m = fmaxf(m, w[j]);
    m = fmaxf(m, __shfl_xor_sync(0xffffffffu, m, 1));
    m = fmaxf(m, __shfl_xor_sync(0xffffffffu, m, 2));
    float s = 0.f;
    #pragma unroll
    for (int j = 0; j < 16; j++) { w[j] = __expf(w[j] - m); s += w[j]; }
    s += __shfl_xor_sync(0xffffffffu, s, 1);
    s += __shfl_xor_sync(0xffffffffu, s, 2);
    float inv = 1.0f / s;
    #pragma unroll
    for (int j = 0; j < 16; j++) w[j] *= inv;

    if (W) {
        float* wout = W + (size_t)blk * 4096 + qi * 64 + kj0;
        #pragma unroll
        for (int j = 0; j < 16; j++) wout[j] = w[j];
    }

    __syncthreads();
    for (int i = tid; i < 4096; i += 256) {
        int r = i >> 6, c = i & 63;
        qs[r][c] = V[base + (size_t)r * DD + c];
    }
    __syncthreads();

    #pragma unroll
    for (int dc = 0; dc < 4; dc++) {
        float p[16];
        #pragma unroll
        for (int jj = 0; jj < 16; jj++) {
            int d = dc * 16 + jj;
            float acc = 0.f;
            #pragma unroll
            for (int j = 0; j < 16; j++)
                acc = fmaf(w[j], qs[kj0 + j][d], acc);
            p[jj] = acc;
        }
        #pragma unroll
        for (int jj = 0; jj < 16; jj++) {
            p[jj] += __shfl_xor_sync(0xffffffffu, p[jj], 1);
            p[jj] += __shfl_xor_sync(0xffffffffu, p[jj], 2);
        }
        if ((tid & 3) == dc) {
            #pragma unroll
            for (int jj = 0; jj < 16; jj++)
                O[base + (size_t)qi * DD + dc * 16 + jj] = p[jj];
        }
    }
}

// ---------------- host launcher ---------------------------------------------
extern "C" void kernel_launch(void* const* d_in, const int* in_sizes, int n_in,
                              void* d_out, int out_size)
{
    const float* hidden = (const float*)d_in[0];
    const float* ln1_g  = (const float*)d_in[1];
    const float* ln1_b  = (const float*)d_in[2];
    const float* ln2_g  = (const float*)d_in[3];
    const float* ln2_b  = (const float*)d_in[4];
    const float* wq = (const float*)d_in[5];  const float* bq = (const float*)d_in[6];
    const float* wk = (const float*)d_in[7];  const float* bk = (const float*)d_in[8];
    const float* wv = (const float*)d_in[9];  const float* bv = (const float*)d_in[10];
    const float* wo = (const float*)d_in[11]; const float* bo = (const float*)d_in[12];
    const float* w1 = (const float*)d_in[13]; const float* b1 = (const float*)d_in[14];
    const float* w2 = (const float*)d_in[15]; const float* b2 = (const float*)d_in[16];
    float* out = (float*)d_out;

    float *x1, *q, *k, *v, *h, *ff;
    float *wqT, *wkT, *wvT, *woT, *w1T, *w2T;
    cudaGetSymbolAddress((void**)&x1, g_x1);
    cudaGetSymbolAddress((void**)&q,  g_q);
    cudaGetSymbolAddress((void**)&k,  g_k);
    cudaGetSymbolAddress((void**)&v,  g_v);
    cudaGetSymbolAddress((void**)&h,  g_h);
    cudaGetSymbolAddress((void**)&ff, g_ff);
    cudaGetSymbolAddress((void**)&wqT, g_wqT);
    cudaGetSymbolAddress((void**)&wkT, g_wkT);
    cudaGetSymbolAddress((void**)&wvT, g_wvT);
    cudaGetSymbolAddress((void**)&woT, g_woT);
    cudaGetSymbolAddress((void**)&w1T, g_w1T);
    cudaGetSymbolAddress((void**)&w2T, g_w2T);

    cudaFuncSetAttribute(tgemm<0>, cudaFuncAttributeMaxDynamicSharedMemorySize, SMEM_BYTES);
    cudaFuncSetAttribute(tgemm<1>, cudaFuncAttributeMaxDynamicSharedMemorySize, SMEM_BYTES);
    cudaFuncSetAttribute(tgemm<2>, cudaFuncAttributeMaxDynamicSharedMemorySize, SMEM_BYTES);

    const int MAIN_ELEMS = MROWS * DD;                 // 8388608
    const int ATTW_ELEMS = BB * HH * NBLK * 64 * 64;   // 8388608
    float* attw = (out_size >= MAIN_ELEMS + ATTW_ELEMS) ? out + MAIN_ELEMS
                                                        : nullptr;

    dim3 tb(32, 8);
    transpose_kernel<<<dim3(DD/32, DD/32), tb>>>(wq, wqT, DD, DD);
    transpose_kernel<<<dim3(DD/32, DD/32), tb>>>(wk, wkT, DD, DD);
    transpose_kernel<<<dim3(DD/32, DD/32), tb>>>(wv, wvT, DD, DD);
    transpose_kernel<<<dim3(DD/32, DD/32), tb>>>(wo, woT, DD, DD);
    transpose_kernel<<<dim3(FF/32, DD/32), tb>>>(w1, w1T, DD, FF);
    transpose_kernel<<<dim3(DD/32, FF/32), tb>>>(w2, w2T, FF, DD);

    dim3 gD(DD / 128, MROWS / 128);   // (8, 64)
    dim3 gF(FF / 128, MROWS / 128);   // (32, 64)

    // x1 = LN1(hidden)
    ln_kernel<<<MROWS, 256>>>(hidden, ln1_g, ln1_b, x1);
    // q/k/v = x1 @ w{q,k,v} + b
    tgemm<0><<<gD, 256, SMEM_BYTES>>>(x1, wqT, bq, nullptr, q, MROWS, DD, DD);
    tgemm<0><<<gD, 256, SMEM_BYTES>>>(x1, wkT, bk, nullptr, k, MROWS, DD, DD);
    tgemm<0><<<gD, 256, SMEM_BYTES>>>(x1, wvT, bv, nullptr, v, MROWS, DD, DD);
    // block attention: O into x1; optional attn_w out
    attention_kernel<<<BB * HH * NBLK, 256>>>(q, k, v, x1, attw);
    // h = hidden + O @ wo + bo
    tgemm<1><<<gD, 256, SMEM_BYTES>>>(x1, woT, bo, hidden, h, MROWS, DD, DD);
    // x2 = LN2(h)  (into q, reuse)
    ln_kernel<<<MROWS, 256>>>(h, ln2_g, ln2_b, q);
    // ff = gelu(x2 @ w1 + b1)
    tgemm<2><<<gF, 256, SMEM_BYTES>>>(q, w1T, b1, nullptr, ff, MROWS, FF, DD);
    // out = h + ff @ w2 + b2
    tgemm<1><<<gD, 256, SMEM_BYTES>>>(ff, w2T, b2, h, out, MROWS, DD, FF);
}